// round 4
// baseline (speedup 1.0000x reference)
// R3: dtype fix — harness promotes fp16->float32 and int8->int32.
// x(f32), qweight(i32), scale/bias(f32), out(f32).
// Pre-passes: W i32->fp16 scratch, x f32->fp16 scratch. HMMA mma.sync GEMM
// (BM=128 BN=128 BK=32, 3-stage cp.async, 80B pitch), fused scale+bias epilogue
// with round-to-fp16 to match reference output exactly.
#include <cuda_runtime.h>
#include <cuda_fp16.h>
#include <cstdint>

static constexpr int IN_F  = 4096;
static constexpr int OUT_F = 11008;
static constexpr int M_TOTAL = 8192;

static constexpr int BM = 128;
static constexpr int BN = 128;
static constexpr int BK = 32;
static constexpr int STAGES = 3;
static constexpr int NIT = IN_F / BK;           // 128

static constexpr int ROW_PITCH = 80;            // 64B data + 16B pad
static constexpr int A_STAGE = BM * ROW_PITCH;
static constexpr int B_STAGE = BN * ROW_PITCH;
static constexpr int STAGE_BYTES = A_STAGE + B_STAGE;     // 20480
static constexpr int SMEM_TOTAL = STAGES * STAGE_BYTES;   // 61440

static constexpr int GRID_M = M_TOTAL / BM;     // 64
static constexpr int GRID_N = OUT_F / BN;       // 86

// fp16 scratch (device globals — no allocation APIs)
__device__ __align__(128) __half g_wf16[(size_t)OUT_F * IN_F];    // 90 MB
__device__ __align__(128) __half g_xf16[(size_t)M_TOTAL * IN_F];  // 64 MB

// ---------------- helpers ----------------
__device__ __forceinline__ uint32_t smem_to_u32(const void* p) {
    uint32_t a;
    asm("{ .reg .u64 t; cvta.to.shared.u64 t, %1; cvt.u32.u64 %0, t; }" : "=r"(a) : "l"(p));
    return a;
}
#define CP_ASYNC16(saddr, gptr) \
    asm volatile("cp.async.cg.shared.global [%0], [%1], 16;" :: "r"((uint32_t)(saddr)), "l"(gptr) : "memory")
#define CP_COMMIT() asm volatile("cp.async.commit_group;" ::: "memory")
#define CP_WAIT1()  asm volatile("cp.async.wait_group 1;"  ::: "memory")

#define LDSM_X4(r0, r1, r2, r3, addr) \
    asm volatile("ldmatrix.sync.aligned.m8n8.x4.shared.b16 {%0,%1,%2,%3}, [%4];" \
        : "=r"(r0), "=r"(r1), "=r"(r2), "=r"(r3) : "r"(addr))

#define MMA16816(d0, d1, d2, d3, a0, a1, a2, a3, b0, b1) \
    asm volatile("mma.sync.aligned.m16n8k16.row.col.f32.f16.f16.f32 " \
        "{%0,%1,%2,%3}, {%4,%5,%6,%7}, {%8,%9}, {%0,%1,%2,%3};" \
        : "+f"(d0), "+f"(d1), "+f"(d2), "+f"(d3) \
        : "r"(a0), "r"(a1), "r"(a2), "r"(a3), "r"(b0), "r"(b1))

// ---------------- pre-pass: W int32 -> fp16 ----------------
__global__ void __launch_bounds__(256) convert_w_kernel(const int* __restrict__ q) {
    size_t i = ((size_t)blockIdx.x * blockDim.x + threadIdx.x) * 8;
    if (i >= (size_t)OUT_F * IN_F) return;
    const int4 v0 = *reinterpret_cast<const int4*>(q + i);
    const int4 v1 = *reinterpret_cast<const int4*>(q + i + 4);
    __half h[8];
    h[0] = __int2half_rn(v0.x); h[1] = __int2half_rn(v0.y);
    h[2] = __int2half_rn(v0.z); h[3] = __int2half_rn(v0.w);
    h[4] = __int2half_rn(v1.x); h[5] = __int2half_rn(v1.y);
    h[6] = __int2half_rn(v1.z); h[7] = __int2half_rn(v1.w);
    *reinterpret_cast<uint4*>(g_wf16 + i) = *reinterpret_cast<const uint4*>(h);
}

// ---------------- pre-pass: x float32 -> fp16 (lossless: values are fp16-origin) ----------------
__global__ void __launch_bounds__(256) convert_x_kernel(const float* __restrict__ x) {
    size_t i = ((size_t)blockIdx.x * blockDim.x + threadIdx.x) * 8;
    if (i >= (size_t)M_TOTAL * IN_F) return;
    const float4 v0 = *reinterpret_cast<const float4*>(x + i);
    const float4 v1 = *reinterpret_cast<const float4*>(x + i + 4);
    __half h[8];
    h[0] = __float2half_rn(v0.x); h[1] = __float2half_rn(v0.y);
    h[2] = __float2half_rn(v0.z); h[3] = __float2half_rn(v0.w);
    h[4] = __float2half_rn(v1.x); h[5] = __float2half_rn(v1.y);
    h[6] = __float2half_rn(v1.z); h[7] = __float2half_rn(v1.w);
    *reinterpret_cast<uint4*>(g_xf16 + i) = *reinterpret_cast<const uint4*>(h);
}

// ---------------- main GEMM ----------------
__global__ void __launch_bounds__(256, 2) w8_gemm_kernel(
    const float* __restrict__ scale,    // [11008] f32
    const float* __restrict__ bias,     // [11008] f32
    float* __restrict__ out)            // [8192, 11008] f32
{
    extern __shared__ __align__(16) char smem_raw[];
    const uint32_t smem = smem_to_u32(smem_raw);

    const int tid  = threadIdx.x;
    const int lane = tid & 31;
    const int wid  = tid >> 5;
    const int warp_m = wid & 1;         // 2 row groups of 64
    const int warp_n = wid >> 1;        // 4 col groups of 32

    const int m0 = blockIdx.x * BM;
    const int n0 = blockIdx.y * BN;

    // --- per-thread cp.async coords (2 chunks each of A and B tile) ---
    const int c0i = tid, c1i = tid + 256;
    const int a_r0 = c0i >> 2, a_c0 = c0i & 3;
    const int a_r1 = c1i >> 2, a_c1 = c1i & 3;
    const uint32_t sA0 = (uint32_t)(a_r0 * ROW_PITCH + a_c0 * 16);
    const uint32_t sA1 = (uint32_t)(a_r1 * ROW_PITCH + a_c1 * 16);
    const __half* gA0 = g_xf16 + (size_t)(m0 + a_r0) * IN_F + a_c0 * 8;
    const __half* gA1 = g_xf16 + (size_t)(m0 + a_r1) * IN_F + a_c1 * 8;
    const __half* gB0 = g_wf16 + (size_t)(n0 + a_r0) * IN_F + a_c0 * 8;
    const __half* gB1 = g_wf16 + (size_t)(n0 + a_r1) * IN_F + a_c1 * 8;

    // --- ldmatrix lane addresses ---
    const uint32_t a_lm = (uint32_t)((warp_m * 64 + (lane & 15)) * ROW_PITCH + (lane >> 4) * 16);
    const uint32_t b_lm = (uint32_t)((warp_n * 32 + (lane & 7) + ((lane >> 4) << 3)) * ROW_PITCH
                                     + ((lane >> 3) & 1) * 16);

    float acc[4][4][4];
#pragma unroll
    for (int mi = 0; mi < 4; mi++)
#pragma unroll
        for (int ni = 0; ni < 4; ni++)
#pragma unroll
            for (int j = 0; j < 4; j++) acc[mi][ni][j] = 0.f;

#pragma unroll
    for (int s = 0; s < STAGES - 1; s++) {
        const uint32_t as = smem + s * STAGE_BYTES;
        const uint32_t bs = as + A_STAGE;
        const int k0 = s * BK;
        CP_ASYNC16(as + sA0, gA0 + k0);
        CP_ASYNC16(as + sA1, gA1 + k0);
        CP_ASYNC16(bs + sA0, gB0 + k0);
        CP_ASYNC16(bs + sA1, gB1 + k0);
        CP_COMMIT();
    }

    int cur = 0, nxt = STAGES - 1;
    for (int it = 0; it < NIT; ++it) {
        CP_WAIT1();
        __syncthreads();

        if (it + STAGES - 1 < NIT) {
            const uint32_t as = smem + nxt * STAGE_BYTES;
            const uint32_t bs = as + A_STAGE;
            const int k0 = (it + STAGES - 1) * BK;
            CP_ASYNC16(as + sA0, gA0 + k0);
            CP_ASYNC16(as + sA1, gA1 + k0);
            CP_ASYNC16(bs + sA0, gB0 + k0);
            CP_ASYNC16(bs + sA1, gB1 + k0);
        }
        CP_COMMIT();

        const uint32_t as = smem + cur * STAGE_BYTES;
        const uint32_t bs = as + A_STAGE;
#pragma unroll
        for (int ks = 0; ks < 2; ks++) {
            uint32_t a[4][4];
#pragma unroll
            for (int mi = 0; mi < 4; mi++)
                LDSM_X4(a[mi][0], a[mi][1], a[mi][2], a[mi][3],
                        as + a_lm + mi * 16 * ROW_PITCH + ks * 32);
            uint32_t b[2][4];
#pragma unroll
            for (int nt = 0; nt < 2; nt++)
                LDSM_X4(b[nt][0], b[nt][1], b[nt][2], b[nt][3],
                        bs + b_lm + nt * 16 * ROW_PITCH + ks * 32);
#pragma unroll
            for (int mi = 0; mi < 4; mi++)
#pragma unroll
                for (int ni = 0; ni < 4; ni++)
                    MMA16816(acc[mi][ni][0], acc[mi][ni][1], acc[mi][ni][2], acc[mi][ni][3],
                             a[mi][0], a[mi][1], a[mi][2], a[mi][3],
                             b[ni >> 1][(ni & 1) * 2], b[ni >> 1][(ni & 1) * 2 + 1]);
        }

        cur = (cur + 1 == STAGES) ? 0 : cur + 1;
        nxt = (nxt + 1 == STAGES) ? 0 : nxt + 1;
        __syncthreads();
    }

    // --- epilogue: y = round_fp16(acc*scale + bias), stored as float32 ---
    const int qr = lane >> 2;
    const int qc = (lane & 3) * 2;
#pragma unroll
    for (int mi = 0; mi < 4; mi++) {
#pragma unroll
        for (int half_m = 0; half_m < 2; half_m++) {
            const int m = m0 + warp_m * 64 + mi * 16 + half_m * 8 + qr;
            float* orow = out + (size_t)m * OUT_F;
#pragma unroll
            for (int ni = 0; ni < 4; ni++) {
                const int n = n0 + warp_n * 32 + ni * 8 + qc;
                const float2 s2 = *reinterpret_cast<const float2*>(scale + n);
                const float2 b2 = *reinterpret_cast<const float2*>(bias + n);
                float y0 = acc[mi][ni][half_m * 2 + 0] * s2.x + b2.x;
                float y1 = acc[mi][ni][half_m * 2 + 1] * s2.y + b2.y;
                // match reference fp16 output rounding exactly
                y0 = __half2float(__float2half_rn(y0));
                y1 = __half2float(__float2half_rn(y1));
                *reinterpret_cast<float2*>(orow + n) = make_float2(y0, y1);
            }
        }
    }
}

// ---------------- launch ----------------
extern "C" void kernel_launch(void* const* d_in, const int* in_sizes, int n_in,
                              void* d_out, int out_size) {
    const float* x     = (const float*)d_in[0];
    const int*   qw    = (const int*)d_in[1];
    const float* scale = (const float*)d_in[2];
    const float* bias  = (const float*)d_in[3];
    float*       out   = (float*)d_out;

    const size_t wtotal = (size_t)OUT_F * IN_F;
    const size_t xtotal = (size_t)M_TOTAL * IN_F;
    convert_w_kernel<<<(int)((wtotal / 8 + 255) / 256), 256>>>(qw);
    convert_x_kernel<<<(int)((xtotal / 8 + 255) / 256), 256>>>(x);

    cudaFuncSetAttribute(w8_gemm_kernel, cudaFuncAttributeMaxDynamicSharedMemorySize, SMEM_TOTAL);
    dim3 grid(GRID_M, GRID_N);
    w8_gemm_kernel<<<grid, 256, SMEM_TOTAL>>>(scale, bias, out);
}

// round 5
// speedup vs baseline: 1.5163x; 1.5163x over previous
// R5: CUTLASS-shape HMMA GEMM — BM=128 BN=256 BK=32, warp tile 64x64 (2x4 warps),
// 4-stage cp.async, single barrier per mainloop iter, 80B-pitch conflict-free smem.
// Pre-passes: W i32->fp16, x f32->fp16. Fused scale+bias epilogue w/ fp16 rounding.
#include <cuda_runtime.h>
#include <cuda_fp16.h>
#include <cstdint>

static constexpr int IN_F  = 4096;
static constexpr int OUT_F = 11008;
static constexpr int M_TOTAL = 8192;

static constexpr int BM = 128;
static constexpr int BN = 256;
static constexpr int BK = 32;
static constexpr int STAGES = 4;
static constexpr int NIT = IN_F / BK;           // 128

static constexpr int ROW_PITCH = 80;            // 64B data + 16B pad (conflict-free)
static constexpr int A_STAGE = BM * ROW_PITCH;  // 10240
static constexpr int B_STAGE = BN * ROW_PITCH;  // 20480
static constexpr int STAGE_BYTES = A_STAGE + B_STAGE;     // 30720
static constexpr int SMEM_TOTAL = STAGES * STAGE_BYTES;   // 122880

static constexpr int GRID_M = M_TOTAL / BM;     // 64
static constexpr int GRID_N = OUT_F / BN;       // 43

// fp16 scratch (device globals — no allocation APIs)
__device__ __align__(128) __half g_wf16[(size_t)OUT_F * IN_F];    // 90 MB
__device__ __align__(128) __half g_xf16[(size_t)M_TOTAL * IN_F];  // 64 MB

// ---------------- helpers ----------------
__device__ __forceinline__ uint32_t smem_to_u32(const void* p) {
    uint32_t a;
    asm("{ .reg .u64 t; cvta.to.shared.u64 t, %1; cvt.u32.u64 %0, t; }" : "=r"(a) : "l"(p));
    return a;
}
#define CP_ASYNC16(saddr, gptr) \
    asm volatile("cp.async.cg.shared.global [%0], [%1], 16;" :: "r"((uint32_t)(saddr)), "l"(gptr) : "memory")
#define CP_COMMIT() asm volatile("cp.async.commit_group;" ::: "memory")
#define CP_WAIT2()  asm volatile("cp.async.wait_group 2;"  ::: "memory")

#define LDSM_X4(r0, r1, r2, r3, addr) \
    asm volatile("ldmatrix.sync.aligned.m8n8.x4.shared.b16 {%0,%1,%2,%3}, [%4];" \
        : "=r"(r0), "=r"(r1), "=r"(r2), "=r"(r3) : "r"(addr))

#define MMA16816(d0, d1, d2, d3, a0, a1, a2, a3, b0, b1) \
    asm volatile("mma.sync.aligned.m16n8k16.row.col.f32.f16.f16.f32 " \
        "{%0,%1,%2,%3}, {%4,%5,%6,%7}, {%8,%9}, {%0,%1,%2,%3};" \
        : "+f"(d0), "+f"(d1), "+f"(d2), "+f"(d3) \
        : "r"(a0), "r"(a1), "r"(a2), "r"(a3), "r"(b0), "r"(b1))

// ---------------- pre-pass: W int32 -> fp16 ----------------
__global__ void __launch_bounds__(256) convert_w_kernel(const int* __restrict__ q) {
    size_t i = ((size_t)blockIdx.x * blockDim.x + threadIdx.x) * 8;
    if (i >= (size_t)OUT_F * IN_F) return;
    const int4 v0 = *reinterpret_cast<const int4*>(q + i);
    const int4 v1 = *reinterpret_cast<const int4*>(q + i + 4);
    __half h[8];
    h[0] = __int2half_rn(v0.x); h[1] = __int2half_rn(v0.y);
    h[2] = __int2half_rn(v0.z); h[3] = __int2half_rn(v0.w);
    h[4] = __int2half_rn(v1.x); h[5] = __int2half_rn(v1.y);
    h[6] = __int2half_rn(v1.z); h[7] = __int2half_rn(v1.w);
    *reinterpret_cast<uint4*>(g_wf16 + i) = *reinterpret_cast<const uint4*>(h);
}

// ---------------- pre-pass: x float32 -> fp16 (lossless) ----------------
__global__ void __launch_bounds__(256) convert_x_kernel(const float* __restrict__ x) {
    size_t i = ((size_t)blockIdx.x * blockDim.x + threadIdx.x) * 8;
    if (i >= (size_t)M_TOTAL * IN_F) return;
    const float4 v0 = *reinterpret_cast<const float4*>(x + i);
    const float4 v1 = *reinterpret_cast<const float4*>(x + i + 4);
    __half h[8];
    h[0] = __float2half_rn(v0.x); h[1] = __float2half_rn(v0.y);
    h[2] = __float2half_rn(v0.z); h[3] = __float2half_rn(v0.w);
    h[4] = __float2half_rn(v1.x); h[5] = __float2half_rn(v1.y);
    h[6] = __float2half_rn(v1.z); h[7] = __float2half_rn(v1.w);
    *reinterpret_cast<uint4*>(g_xf16 + i) = *reinterpret_cast<const uint4*>(h);
}

// ---------------- main GEMM ----------------
__global__ void __launch_bounds__(256, 1) w8_gemm_kernel(
    const float* __restrict__ scale,    // [11008]
    const float* __restrict__ bias,     // [11008]
    float* __restrict__ out)            // [8192, 11008]
{
    extern __shared__ __align__(16) char smem_raw[];
    const uint32_t smem = smem_to_u32(smem_raw);

    const int tid  = threadIdx.x;
    const int lane = tid & 31;
    const int wid  = tid >> 5;
    const int warp_m = wid & 1;         // 2 row groups of 64
    const int warp_n = wid >> 1;        // 4 col groups of 64

    const int m0 = blockIdx.x * BM;
    const int n0 = blockIdx.y * BN;

    // --- cp.async coords ---
    // A: 128 rows x 4 chunks = 512 chunks; 2/thread.
    // B: 256 rows x 4 chunks = 1024 chunks; 4/thread.
    const int a_r0 = tid >> 2,          a_c0 = tid & 3;
    const int a_r1 = (tid + 256) >> 2,  a_c1 = (tid + 256) & 3;
    const uint32_t sAo0 = (uint32_t)(a_r0 * ROW_PITCH + a_c0 * 16);
    const uint32_t sAo1 = (uint32_t)(a_r1 * ROW_PITCH + a_c1 * 16);
    const __half* gA0 = g_xf16 + (size_t)(m0 + a_r0) * IN_F + a_c0 * 8;
    const __half* gA1 = g_xf16 + (size_t)(m0 + a_r1) * IN_F + a_c1 * 8;
    const __half* gB[4];
    uint32_t sBo[4];
#pragma unroll
    for (int j = 0; j < 4; j++) {
        const int c = tid + 256 * j;
        const int r = c >> 2, ch = c & 3;
        sBo[j] = (uint32_t)(r * ROW_PITCH + ch * 16);
        gB[j] = g_wf16 + (size_t)(n0 + r) * IN_F + ch * 8;
    }

    // --- ldmatrix lane addresses ---
    // A: row = warp_m*64 + (lane&15), chunk = lane>>4 ; +mi*16 rows ; +ks*32 bytes
    const uint32_t a_lm = (uint32_t)((warp_m * 64 + (lane & 15)) * ROW_PITCH + (lane >> 4) * 16);
    // B: row = warp_n*64 + (lane&7) + ((lane>>4)<<3), chunk = (lane>>3)&1 ; +nt*16 rows ; +ks*32 bytes
    const uint32_t b_lm = (uint32_t)((warp_n * 64 + (lane & 7) + ((lane >> 4) << 3)) * ROW_PITCH
                                     + ((lane >> 3) & 1) * 16);

    float acc[4][8][4];
#pragma unroll
    for (int mi = 0; mi < 4; mi++)
#pragma unroll
        for (int ni = 0; ni < 8; ni++)
#pragma unroll
            for (int j = 0; j < 4; j++) acc[mi][ni][j] = 0.f;

    // --- prologue: fill stages 0..STAGES-2 ---
#pragma unroll
    for (int s = 0; s < STAGES - 1; s++) {
        const uint32_t as = smem + s * STAGE_BYTES;
        const uint32_t bs = as + A_STAGE;
        const int k0 = s * BK;
        CP_ASYNC16(as + sAo0, gA0 + k0);
        CP_ASYNC16(as + sAo1, gA1 + k0);
#pragma unroll
        for (int j = 0; j < 4; j++) CP_ASYNC16(bs + sBo[j], gB[j] + k0);
        CP_COMMIT();
    }

    int cur = 0, nxt = STAGES - 1;
    for (int it = 0; it < NIT; ++it) {
        CP_WAIT2();
        __syncthreads();   // publishes stage cur; fences all warps past compute(it-1)

        // load stage for it+STAGES-1 into nxt (consumed at it-1 — safe after barrier)
        if (it + STAGES - 1 < NIT) {
            const uint32_t as = smem + nxt * STAGE_BYTES;
            const uint32_t bs = as + A_STAGE;
            const int k0 = (it + STAGES - 1) * BK;
            CP_ASYNC16(as + sAo0, gA0 + k0);
            CP_ASYNC16(as + sAo1, gA1 + k0);
#pragma unroll
            for (int j = 0; j < 4; j++) CP_ASYNC16(bs + sBo[j], gB[j] + k0);
        }
        CP_COMMIT();

        const uint32_t as = smem + cur * STAGE_BYTES;
        const uint32_t bs = as + A_STAGE;
#pragma unroll
        for (int ks = 0; ks < 2; ks++) {
            uint32_t a[4][4];
#pragma unroll
            for (int mi = 0; mi < 4; mi++)
                LDSM_X4(a[mi][0], a[mi][1], a[mi][2], a[mi][3],
                        as + a_lm + mi * 16 * ROW_PITCH + ks * 32);
            uint32_t b[4][4];
#pragma unroll
            for (int nt = 0; nt < 4; nt++)
                LDSM_X4(b[nt][0], b[nt][1], b[nt][2], b[nt][3],
                        bs + b_lm + nt * 16 * ROW_PITCH + ks * 32);
#pragma unroll
            for (int mi = 0; mi < 4; mi++)
#pragma unroll
                for (int ni = 0; ni < 8; ni++)
                    MMA16816(acc[mi][ni][0], acc[mi][ni][1], acc[mi][ni][2], acc[mi][ni][3],
                             a[mi][0], a[mi][1], a[mi][2], a[mi][3],
                             b[ni >> 1][(ni & 1) * 2], b[ni >> 1][(ni & 1) * 2 + 1]);
        }

        cur = (cur + 1 == STAGES) ? 0 : cur + 1;
        nxt = (nxt + 1 == STAGES) ? 0 : nxt + 1;
    }

    // --- epilogue: y = round_fp16(acc*scale + bias) as float32 ---
    const int qr = lane >> 2;
    const int qc = (lane & 3) * 2;
#pragma unroll
    for (int mi = 0; mi < 4; mi++) {
#pragma unroll
        for (int half_m = 0; half_m < 2; half_m++) {
            const int m = m0 + warp_m * 64 + mi * 16 + half_m * 8 + qr;
            float* orow = out + (size_t)m * OUT_F;
#pragma unroll
            for (int ni = 0; ni < 8; ni++) {
                const int n = n0 + warp_n * 64 + ni * 8 + qc;
                const float2 s2 = *reinterpret_cast<const float2*>(scale + n);
                const float2 b2 = *reinterpret_cast<const float2*>(bias + n);
                float y0 = acc[mi][ni][half_m * 2 + 0] * s2.x + b2.x;
                float y1 = acc[mi][ni][half_m * 2 + 1] * s2.y + b2.y;
                y0 = __half2float(__float2half_rn(y0));
                y1 = __half2float(__float2half_rn(y1));
                *reinterpret_cast<float2*>(orow + n) = make_float2(y0, y1);
            }
        }
    }
}

// ---------------- launch ----------------
extern "C" void kernel_launch(void* const* d_in, const int* in_sizes, int n_in,
                              void* d_out, int out_size) {
    const float* x     = (const float*)d_in[0];
    const int*   qw    = (const int*)d_in[1];
    const float* scale = (const float*)d_in[2];
    const float* bias  = (const float*)d_in[3];
    float*       out   = (float*)d_out;

    const size_t wtotal = (size_t)OUT_F * IN_F;
    const size_t xtotal = (size_t)M_TOTAL * IN_F;
    convert_w_kernel<<<(int)((wtotal / 8 + 255) / 256), 256>>>(qw);
    convert_x_kernel<<<(int)((xtotal / 8 + 255) / 256), 256>>>(x);

    cudaFuncSetAttribute(w8_gemm_kernel, cudaFuncAttributeMaxDynamicSharedMemorySize, SMEM_TOTAL);
    dim3 grid(GRID_M, GRID_N);
    w8_gemm_kernel<<<grid, 256, SMEM_TOTAL>>>(scale, bias, out);
}

// round 6
// speedup vs baseline: 1.5760x; 1.0394x over previous
// R6: 2 CTAs/SM — BM=128 BN=128 BK=64, 128 thr (4 warps, 64x64 warp tile),
// 3-stage cp.async, 144B pitch, single barrier/iter. Pre-passes unchanged.
#include <cuda_runtime.h>
#include <cuda_fp16.h>
#include <cstdint>

static constexpr int IN_F  = 4096;
static constexpr int OUT_F = 11008;
static constexpr int M_TOTAL = 8192;

static constexpr int BM = 128;
static constexpr int BN = 128;
static constexpr int BK = 64;
static constexpr int STAGES = 3;
static constexpr int NIT = IN_F / BK;           // 64

static constexpr int ROW_PITCH = 144;           // 128B data + 16B pad (conflict-free)
static constexpr int A_STAGE = BM * ROW_PITCH;  // 18432
static constexpr int B_STAGE = BN * ROW_PITCH;  // 18432
static constexpr int STAGE_BYTES = A_STAGE + B_STAGE;     // 36864
static constexpr int SMEM_TOTAL = STAGES * STAGE_BYTES;   // 110592 (x2 CTA = 221184)

static constexpr int GRID_M = M_TOTAL / BM;     // 64
static constexpr int GRID_N = OUT_F / BN;       // 86

// fp16 scratch (device globals — no allocation APIs)
__device__ __align__(128) __half g_wf16[(size_t)OUT_F * IN_F];    // 90 MB
__device__ __align__(128) __half g_xf16[(size_t)M_TOTAL * IN_F];  // 64 MB

// ---------------- helpers ----------------
__device__ __forceinline__ uint32_t smem_to_u32(const void* p) {
    uint32_t a;
    asm("{ .reg .u64 t; cvta.to.shared.u64 t, %1; cvt.u32.u64 %0, t; }" : "=r"(a) : "l"(p));
    return a;
}
#define CP_ASYNC16(saddr, gptr) \
    asm volatile("cp.async.cg.shared.global [%0], [%1], 16;" :: "r"((uint32_t)(saddr)), "l"(gptr) : "memory")
#define CP_COMMIT() asm volatile("cp.async.commit_group;" ::: "memory")
#define CP_WAIT1()  asm volatile("cp.async.wait_group 1;"  ::: "memory")

#define LDSM_X4(r0, r1, r2, r3, addr) \
    asm volatile("ldmatrix.sync.aligned.m8n8.x4.shared.b16 {%0,%1,%2,%3}, [%4];" \
        : "=r"(r0), "=r"(r1), "=r"(r2), "=r"(r3) : "r"(addr))

#define MMA16816(d0, d1, d2, d3, a0, a1, a2, a3, b0, b1) \
    asm volatile("mma.sync.aligned.m16n8k16.row.col.f32.f16.f16.f32 " \
        "{%0,%1,%2,%3}, {%4,%5,%6,%7}, {%8,%9}, {%0,%1,%2,%3};" \
        : "+f"(d0), "+f"(d1), "+f"(d2), "+f"(d3) \
        : "r"(a0), "r"(a1), "r"(a2), "r"(a3), "r"(b0), "r"(b1))

// ---------------- pre-pass: W int32 -> fp16 ----------------
__global__ void __launch_bounds__(256) convert_w_kernel(const int* __restrict__ q) {
    size_t i = ((size_t)blockIdx.x * blockDim.x + threadIdx.x) * 8;
    if (i >= (size_t)OUT_F * IN_F) return;
    const int4 v0 = *reinterpret_cast<const int4*>(q + i);
    const int4 v1 = *reinterpret_cast<const int4*>(q + i + 4);
    __half h[8];
    h[0] = __int2half_rn(v0.x); h[1] = __int2half_rn(v0.y);
    h[2] = __int2half_rn(v0.z); h[3] = __int2half_rn(v0.w);
    h[4] = __int2half_rn(v1.x); h[5] = __int2half_rn(v1.y);
    h[6] = __int2half_rn(v1.z); h[7] = __int2half_rn(v1.w);
    *reinterpret_cast<uint4*>(g_wf16 + i) = *reinterpret_cast<const uint4*>(h);
}

// ---------------- pre-pass: x float32 -> fp16 (lossless) ----------------
__global__ void __launch_bounds__(256) convert_x_kernel(const float* __restrict__ x) {
    size_t i = ((size_t)blockIdx.x * blockDim.x + threadIdx.x) * 8;
    if (i >= (size_t)M_TOTAL * IN_F) return;
    const float4 v0 = *reinterpret_cast<const float4*>(x + i);
    const float4 v1 = *reinterpret_cast<const float4*>(x + i + 4);
    __half h[8];
    h[0] = __float2half_rn(v0.x); h[1] = __float2half_rn(v0.y);
    h[2] = __float2half_rn(v0.z); h[3] = __float2half_rn(v0.w);
    h[4] = __float2half_rn(v1.x); h[5] = __float2half_rn(v1.y);
    h[6] = __float2half_rn(v1.z); h[7] = __float2half_rn(v1.w);
    *reinterpret_cast<uint4*>(g_xf16 + i) = *reinterpret_cast<const uint4*>(h);
}

// ---------------- main GEMM ----------------
__global__ void __launch_bounds__(128, 2) w8_gemm_kernel(
    const float* __restrict__ scale,    // [11008]
    const float* __restrict__ bias,     // [11008]
    float* __restrict__ out)            // [8192, 11008]
{
    extern __shared__ __align__(16) char smem_raw[];
    const uint32_t smem = smem_to_u32(smem_raw);

    const int tid  = threadIdx.x;
    const int lane = tid & 31;
    const int wid  = tid >> 5;
    const int warp_m = wid & 1;         // 2 row groups of 64
    const int warp_n = wid >> 1;        // 2 col groups of 64

    const int m0 = blockIdx.x * BM;
    const int n0 = blockIdx.y * BN;

    // --- cp.async coords ---
    // Tile = 128 rows x 8 chunks(16B). 1024 chunks / 128 thr = 8 per thread.
    // chunk j: row = (tid>>3) + 16*j, ch = tid&7.
    const int base_r = tid >> 3;
    const int ch     = tid & 7;
    const uint32_t sOff0 = (uint32_t)(base_r * ROW_PITCH + ch * 16);   // +j*16*ROW_PITCH
    const __half* gA0 = g_xf16 + (size_t)(m0 + base_r) * IN_F + ch * 8; // +j*16*IN_F
    const __half* gB0 = g_wf16 + (size_t)(n0 + base_r) * IN_F + ch * 8;

    // --- ldmatrix lane addresses ---
    // A: row = warp_m*64 + (lane&15), 16B-chunk = lane>>4 ; +mi*16 rows ; +ks*32B
    const uint32_t a_lm = (uint32_t)((warp_m * 64 + (lane & 15)) * ROW_PITCH + (lane >> 4) * 16);
    // B: row = warp_n*64 + (lane&7) + ((lane>>4)<<3), chunk = (lane>>3)&1 ; +nt*16 rows ; +ks*32B
    const uint32_t b_lm = (uint32_t)((warp_n * 64 + (lane & 7) + ((lane >> 4) << 3)) * ROW_PITCH
                                     + ((lane >> 3) & 1) * 16);

    float acc[4][8][4];
#pragma unroll
    for (int mi = 0; mi < 4; mi++)
#pragma unroll
        for (int ni = 0; ni < 8; ni++)
#pragma unroll
            for (int j = 0; j < 4; j++) acc[mi][ni][j] = 0.f;

    // --- prologue: stages 0,1 ---
#pragma unroll
    for (int s = 0; s < STAGES - 1; s++) {
        const uint32_t as = smem + s * STAGE_BYTES;
        const uint32_t bs = as + A_STAGE;
        const int k0 = s * BK;
#pragma unroll
        for (int j = 0; j < 8; j++) {
            CP_ASYNC16(as + sOff0 + j * 16 * ROW_PITCH, gA0 + (size_t)j * 16 * IN_F + k0);
            CP_ASYNC16(bs + sOff0 + j * 16 * ROW_PITCH, gB0 + (size_t)j * 16 * IN_F + k0);
        }
        CP_COMMIT();
    }

    int cur = 0, nxt = STAGES - 1;
    for (int it = 0; it < NIT; ++it) {
        CP_WAIT1();
        __syncthreads();   // publishes stage cur; fences all warps past compute(it-1)

        if (it + STAGES - 1 < NIT) {
            const uint32_t as = smem + nxt * STAGE_BYTES;
            const uint32_t bs = as + A_STAGE;
            const int k0 = (it + STAGES - 1) * BK;
#pragma unroll
            for (int j = 0; j < 8; j++) {
                CP_ASYNC16(as + sOff0 + j * 16 * ROW_PITCH, gA0 + (size_t)j * 16 * IN_F + k0);
                CP_ASYNC16(bs + sOff0 + j * 16 * ROW_PITCH, gB0 + (size_t)j * 16 * IN_F + k0);
            }
        }
        CP_COMMIT();

        const uint32_t as = smem + cur * STAGE_BYTES;
        const uint32_t bs = as + A_STAGE;
#pragma unroll
        for (int ks = 0; ks < 4; ks++) {
            uint32_t a[4][4];
#pragma unroll
            for (int mi = 0; mi < 4; mi++)
                LDSM_X4(a[mi][0], a[mi][1], a[mi][2], a[mi][3],
                        as + a_lm + mi * 16 * ROW_PITCH + ks * 32);
            uint32_t b[4][4];
#pragma unroll
            for (int nt = 0; nt < 4; nt++)
                LDSM_X4(b[nt][0], b[nt][1], b[nt][2], b[nt][3],
                        bs + b_lm + nt * 16 * ROW_PITCH + ks * 32);
#pragma unroll
            for (int mi = 0; mi < 4; mi++)
#pragma unroll
                for (int ni = 0; ni < 8; ni++)
                    MMA16816(acc[mi][ni][0], acc[mi][ni][1], acc[mi][ni][2], acc[mi][ni][3],
                             a[mi][0], a[mi][1], a[mi][2], a[mi][3],
                             b[ni >> 1][(ni & 1) * 2], b[ni >> 1][(ni & 1) * 2 + 1]);
        }

        cur = (cur + 1 == STAGES) ? 0 : cur + 1;
        nxt = (nxt + 1 == STAGES) ? 0 : nxt + 1;
    }

    // --- epilogue: y = round_fp16(acc*scale + bias) as float32 ---
    const int qr = lane >> 2;
    const int qc = (lane & 3) * 2;
#pragma unroll
    for (int mi = 0; mi < 4; mi++) {
#pragma unroll
        for (int half_m = 0; half_m < 2; half_m++) {
            const int m = m0 + warp_m * 64 + mi * 16 + half_m * 8 + qr;
            float* orow = out + (size_t)m * OUT_F;
#pragma unroll
            for (int ni = 0; ni < 8; ni++) {
                const int n = n0 + warp_n * 64 + ni * 8 + qc;
                const float2 s2 = *reinterpret_cast<const float2*>(scale + n);
                const float2 b2 = *reinterpret_cast<const float2*>(bias + n);
                float y0 = acc[mi][ni][half_m * 2 + 0] * s2.x + b2.x;
                float y1 = acc[mi][ni][half_m * 2 + 1] * s2.y + b2.y;
                y0 = __half2float(__float2half_rn(y0));
                y1 = __half2float(__float2half_rn(y1));
                *reinterpret_cast<float2*>(orow + n) = make_float2(y0, y1);
            }
        }
    }
}

// ---------------- launch ----------------
extern "C" void kernel_launch(void* const* d_in, const int* in_sizes, int n_in,
                              void* d_out, int out_size) {
    const float* x     = (const float*)d_in[0];
    const int*   qw    = (const int*)d_in[1];
    const float* scale = (const float*)d_in[2];
    const float* bias  = (const float*)d_in[3];
    float*       out   = (float*)d_out;

    const size_t wtotal = (size_t)OUT_F * IN_F;
    const size_t xtotal = (size_t)M_TOTAL * IN_F;
    convert_w_kernel<<<(int)((wtotal / 8 + 255) / 256), 256>>>(qw);
    convert_x_kernel<<<(int)((xtotal / 8 + 255) / 256), 256>>>(x);

    cudaFuncSetAttribute(w8_gemm_kernel, cudaFuncAttributeMaxDynamicSharedMemorySize, SMEM_TOTAL);
    dim3 grid(GRID_M, GRID_N);
    w8_gemm_kernel<<<grid, 128, SMEM_TOTAL>>>(scale, bias, out);
}